// round 5
// baseline (speedup 1.0000x reference)
#include <cuda_runtime.h>
#include <cuda_bf16.h>
#include <cstdint>

#define BHALF 4096
#define NROW  8192
#define DIM   256
#define INV_T (1.0f/0.07f)
#define LOG2E 1.4426950408889634f
#define QSCALE 127.0f
#define DEQ (1.0f/(QSCALE*QSCALE))          // acc -> sim
#define KQ  (DEQ * INV_T * LOG2E)           // acc -> log2-domain logit

#define TILE_M 128
#define TILE_N 128
#define STRIDE_B 272                          // 256 + 16 byte pad (conflict-free)
#define SMEM_BYTES (2 * TILE_M * STRIDE_B)    // 69632: A + B tiles (int8)

__device__ int8_t g_zn[NROW * DIM];           // normalized rows, s8 (2 MB)
__device__ float g_sumexp[NROW];
__device__ float g_pos[NROW];

// ---------------------------------------------------------------------------
// Kernel A: L2-normalize rows of concat(z_i, z_j) -> s8 (scale 127)
// ---------------------------------------------------------------------------
__global__ void normalize_kernel(const float* __restrict__ z_i,
                                 const float* __restrict__ z_j) {
    int warp = threadIdx.x >> 5, lane = threadIdx.x & 31;
    int row  = blockIdx.x * 8 + warp;
    const float* src = (row < BHALF) ? (z_i + (size_t)row * DIM)
                                     : (z_j + (size_t)(row - BHALF) * DIM);
    float4 v0 = ((const float4*)src)[lane * 2];
    float4 v1 = ((const float4*)src)[lane * 2 + 1];
    float ss = v0.x*v0.x + v0.y*v0.y + v0.z*v0.z + v0.w*v0.w
             + v1.x*v1.x + v1.y*v1.y + v1.z*v1.z + v1.w*v1.w;
    #pragma unroll
    for (int o = 16; o; o >>= 1) ss += __shfl_xor_sync(0xffffffffu, ss, o);
    float inv = QSCALE / fmaxf(sqrtf(ss), 1e-8f);

    int q0 = __float2int_rn(v0.x*inv), q1 = __float2int_rn(v0.y*inv);
    int q2 = __float2int_rn(v0.z*inv), q3 = __float2int_rn(v0.w*inv);
    int q4 = __float2int_rn(v1.x*inv), q5 = __float2int_rn(v1.y*inv);
    int q6 = __float2int_rn(v1.z*inv), q7 = __float2int_rn(v1.w*inv);
    unsigned lo = (q0 & 0xff) | ((q1 & 0xff) << 8) | ((q2 & 0xff) << 16) | (q3 << 24);
    unsigned hi = (q4 & 0xff) | ((q5 & 0xff) << 8) | ((q6 & 0xff) << 16) | (q7 << 24);
    uint2 u; u.x = lo; u.y = hi;
    *(uint2*)(g_zn + (size_t)row * DIM + lane * 8) = u;
    if (lane == 0) { g_sumexp[row] = 0.0f; g_pos[row] = 0.0f; }
}

// ---------------------------------------------------------------------------
// fast exp via 2^y on the FMA pipe
// ---------------------------------------------------------------------------
__device__ __forceinline__ float fast_exp2(float y) {
    float t  = y + 12582912.0f;          // round-to-nearest-int trick (1.5*2^23)
    int   i  = __float_as_int(t);
    float nf = t - 12582912.0f;
    float f  = y - nf;                   // f in [-0.5, 0.5]
    float p  = fmaf(1.3333558e-3f, f, 9.6181291e-3f);
    p = fmaf(p, f, 5.5504109e-2f);
    p = fmaf(p, f, 2.4022651e-1f);
    p = fmaf(p, f, 6.9314718e-1f);
    p = fmaf(p, f, 1.0f);
    return p * __int_as_float((i << 23) + 0x3F800000);
}

__device__ __forceinline__ void mma_s8(int c[4],
                                       unsigned a0, unsigned a1, unsigned a2, unsigned a3,
                                       unsigned b0, unsigned b1) {
    asm volatile(
        "mma.sync.aligned.m16n8k32.row.col.s32.s8.s8.s32 "
        "{%0,%1,%2,%3}, {%4,%5,%6,%7}, {%8,%9}, {%0,%1,%2,%3};\n"
        : "+r"(c[0]), "+r"(c[1]), "+r"(c[2]), "+r"(c[3])
        : "r"(a0), "r"(a1), "r"(a2), "r"(a3), "r"(b0), "r"(b1));
}

// ---------------------------------------------------------------------------
// Kernel B: symmetric s8 IMMA GEMM (upper-triangle tiles) with fused
// exp + diagonal mask + row AND column sum-of-exp.
// grid: (64 row-tiles, 4 column slices); tiles with j < i skipped.
// 2 CTAs/SM co-residency hides tile-load latency.
// ---------------------------------------------------------------------------
__global__ void __launch_bounds__(256, 2) ntxent_gemm_kernel() {
    extern __shared__ int8_t smem[];
    int8_t* As = smem;
    int8_t* Bs = smem + TILE_M * STRIDE_B;

    int tid  = threadIdx.x;
    int warp = tid >> 5, lane = tid & 31;
    int g    = lane >> 2, tig = lane & 3;
    int wm   = warp >> 2, wn = warp & 3;      // 2x4 warp grid -> 64x32 per warp

    int iTile   = blockIdx.x;
    int rowbase = iTile * TILE_M;

    // Load A tile (128 x 256 s8 = 32 KB)
    {
        const uint4* gsrc = (const uint4*)(g_zn + (size_t)rowbase * DIM);
        #pragma unroll
        for (int it = 0; it < 8; it++) {
            int idx = tid + it * 256;           // 2048 16B chunks
            int r = idx >> 4, c = idx & 15;
            *(uint4*)(As + r * STRIDE_B + c * 16) = gsrc[r * 16 + c];
        }
    }

    float rsum[4][2];
    #pragma unroll
    for (int mt = 0; mt < 4; mt++) { rsum[mt][0] = 0.f; rsum[mt][1] = 0.f; }

    bool didWork = false;

    for (int t = 0; t < 16; t++) {
        int jTile = blockIdx.y * 16 + t;
        if (jTile < iTile) continue;          // symmetry: upper triangle only
        didWork = true;
        int colbase = jTile * TILE_M;

        __syncthreads();   // previous tile's compute done
        {
            const uint4* gsrc = (const uint4*)(g_zn + (size_t)colbase * DIM);
            #pragma unroll
            for (int it = 0; it < 8; it++) {
                int idx = tid + it * 256;
                int r = idx >> 4, c = idx & 15;
                *(uint4*)(Bs + r * STRIDE_B + c * 16) = gsrc[r * 16 + c];
            }
        }
        __syncthreads();

        int acc[4][4][4];
        #pragma unroll
        for (int mt = 0; mt < 4; mt++)
            #pragma unroll
            for (int nt = 0; nt < 4; nt++)
                #pragma unroll
                for (int ci = 0; ci < 4; ci++) acc[mt][nt][ci] = 0;

        #pragma unroll
        for (int kk = 0; kk < 8; kk++) {
            int k0 = kk * 32 + tig * 4;
            unsigned a[4][4], b[4][2];
            #pragma unroll
            for (int mt = 0; mt < 4; mt++) {
                const int8_t* ap = As + (wm * 64 + mt * 16 + g) * STRIDE_B + k0;
                a[mt][0] = *(const unsigned*)(ap);
                a[mt][1] = *(const unsigned*)(ap + 8 * STRIDE_B);
                a[mt][2] = *(const unsigned*)(ap + 16);
                a[mt][3] = *(const unsigned*)(ap + 8 * STRIDE_B + 16);
            }
            #pragma unroll
            for (int nt = 0; nt < 4; nt++) {
                const int8_t* bp = Bs + (wn * 32 + nt * 8 + g) * STRIDE_B + k0;
                b[nt][0] = *(const unsigned*)(bp);
                b[nt][1] = *(const unsigned*)(bp + 16);
            }
            #pragma unroll
            for (int mt = 0; mt < 4; mt++)
                #pragma unroll
                for (int nt = 0; nt < 4; nt++)
                    mma_s8(acc[mt][nt], a[mt][0], a[mt][1], a[mt][2], a[mt][3],
                           b[nt][0], b[nt][1]);
        }

        if (jTile == iTile) {
            // Diagonal tile: row sums only, exact diagonal mask.
            #pragma unroll
            for (int mt = 0; mt < 4; mt++) {
                int row0 = rowbase + wm * 64 + mt * 16 + g;
                #pragma unroll
                for (int nt = 0; nt < 4; nt++) {
                    int col0 = colbase + wn * 32 + nt * 8 + tig * 2;
                    #pragma unroll
                    for (int ci = 0; ci < 4; ci++) {
                        int row = row0 + (ci >> 1) * 8;
                        int col = col0 + (ci & 1);
                        float e = fast_exp2((float)acc[mt][nt][ci] * KQ);
                        if (col == row) e = 0.0f;
                        rsum[mt][ci >> 1] += e;
                    }
                }
            }
        } else {
            float csum[4][2];
            #pragma unroll
            for (int nt = 0; nt < 4; nt++) { csum[nt][0] = 0.f; csum[nt][1] = 0.f; }

            bool hasPos = (jTile == iTile + 32);   // contains sim[r, r+4096]
            if (hasPos) {
                #pragma unroll
                for (int mt = 0; mt < 4; mt++) {
                    int row0 = rowbase + wm * 64 + mt * 16 + g;
                    #pragma unroll
                    for (int nt = 0; nt < 4; nt++) {
                        int col0 = colbase + wn * 32 + nt * 8 + tig * 2;
                        #pragma unroll
                        for (int ci = 0; ci < 4; ci++) {
                            int row = row0 + (ci >> 1) * 8;
                            int col = col0 + (ci & 1);
                            float v = (float)acc[mt][nt][ci];
                            float e = fast_exp2(v * KQ);
                            if (col == row + BHALF) {      // positive pair (both dirs)
                                float pv = v * (DEQ * INV_T);
                                g_pos[row] = pv;
                                g_pos[col] = pv;
                            }
                            rsum[mt][ci >> 1] += e;
                            csum[nt][ci & 1]  += e;
                        }
                    }
                }
            } else {
                #pragma unroll
                for (int mt = 0; mt < 4; mt++) {
                    #pragma unroll
                    for (int nt = 0; nt < 4; nt++) {
                        #pragma unroll
                        for (int ci = 0; ci < 4; ci++) {
                            float e = fast_exp2((float)acc[mt][nt][ci] * KQ);
                            rsum[mt][ci >> 1] += e;
                            csum[nt][ci & 1]  += e;
                        }
                    }
                }
            }

            // Column reduction: sum over g lanes (xor 4,8,16), then atomic.
            #pragma unroll
            for (int nt = 0; nt < 4; nt++) {
                #pragma unroll
                for (int p = 0; p < 2; p++) {
                    float v = csum[nt][p];
                    v += __shfl_xor_sync(0xffffffffu, v, 4);
                    v += __shfl_xor_sync(0xffffffffu, v, 8);
                    v += __shfl_xor_sync(0xffffffffu, v, 16);
                    if (g == 0) {
                        int col = colbase + wn * 32 + nt * 8 + tig * 2 + p;
                        atomicAdd(&g_sumexp[col], v);
                    }
                }
            }
        }
    }

    if (!didWork) return;

    // Reduce row sums across the 4 lanes (tig) sharing each row, then global
    #pragma unroll
    for (int mt = 0; mt < 4; mt++) {
        #pragma unroll
        for (int h = 0; h < 2; h++) {
            float v = rsum[mt][h];
            v += __shfl_xor_sync(0xffffffffu, v, 1);
            v += __shfl_xor_sync(0xffffffffu, v, 2);
            if (tig == 0) {
                int row = rowbase + wm * 64 + mt * 16 + g + h * 8;
                atomicAdd(&g_sumexp[row], v);
            }
        }
    }
}

// ---------------------------------------------------------------------------
// Kernel C: loss = mean_k( log(sumexp_k) - pos_k )
// ---------------------------------------------------------------------------
__global__ void loss_kernel(float* __restrict__ out) {
    int tid = threadIdx.x;  // 1024
    float s = 0.0f;
    for (int k = tid; k < NROW; k += 1024)
        s += logf(g_sumexp[k]) - g_pos[k];
    #pragma unroll
    for (int o = 16; o; o >>= 1) s += __shfl_xor_sync(0xffffffffu, s, o);
    __shared__ float sw[32];
    if ((tid & 31) == 0) sw[tid >> 5] = s;
    __syncthreads();
    if (tid < 32) {
        float v = sw[tid];
        #pragma unroll
        for (int o = 16; o; o >>= 1) v += __shfl_xor_sync(0xffffffffu, v, o);
        if (tid == 0) out[0] = v / (float)NROW;
    }
}

extern "C" void kernel_launch(void* const* d_in, const int* in_sizes, int n_in,
                              void* d_out, int out_size) {
    const float* z_i = (const float*)d_in[0];
    const float* z_j = (const float*)d_in[1];
    float* out = (float*)d_out;

    cudaFuncSetAttribute(ntxent_gemm_kernel,
                         cudaFuncAttributeMaxDynamicSharedMemorySize, SMEM_BYTES);

    normalize_kernel<<<NROW / 8, 256>>>(z_i, z_j);
    ntxent_gemm_kernel<<<dim3(64, 4), 256, SMEM_BYTES>>>();
    loss_kernel<<<1, 1024>>>(out);
}

// round 6
// speedup vs baseline: 2.1081x; 2.1081x over previous
#include <cuda_runtime.h>
#include <cuda_bf16.h>

#define BHALF 4096
#define NROW  8192
#define DIM   256
#define INV_T (1.0f/0.07f)
#define LOG2E 1.4426950408889634f

#define TILE_M 128
#define TILE_N 128
#define A_STRIDE 264             // bf16 units: 256 + 8 pad, conflict-free
#define B_STRIDE 136             // bf16 units: 128 + 8 pad, conflict-free
#define SMEM_BYTES (TILE_M * A_STRIDE * 2 + TILE_N * B_STRIDE * 2)  // 102400

__device__ __nv_bfloat16 g_zn[NROW * DIM];   // normalized rows, bf16 (4 MB)
__device__ float g_sumexp[NROW];
__device__ float g_pos[NROW];

// ---------------------------------------------------------------------------
// Kernel A: L2-normalize rows of concat(z_i, z_j) -> bf16; zero accumulators
// ---------------------------------------------------------------------------
__global__ void normalize_kernel(const float* __restrict__ z_i,
                                 const float* __restrict__ z_j) {
    int warp = threadIdx.x >> 5, lane = threadIdx.x & 31;
    int row  = blockIdx.x * 8 + warp;
    const float* src = (row < BHALF) ? (z_i + (size_t)row * DIM)
                                     : (z_j + (size_t)(row - BHALF) * DIM);
    float4 v0 = ((const float4*)src)[lane * 2];
    float4 v1 = ((const float4*)src)[lane * 2 + 1];
    float ss = v0.x*v0.x + v0.y*v0.y + v0.z*v0.z + v0.w*v0.w
             + v1.x*v1.x + v1.y*v1.y + v1.z*v1.z + v1.w*v1.w;
    #pragma unroll
    for (int o = 16; o; o >>= 1) ss += __shfl_xor_sync(0xffffffffu, ss, o);
    float inv = 1.0f / fmaxf(sqrtf(ss), 1e-8f);

    __nv_bfloat162 h0 = __floats2bfloat162_rn(v0.x*inv, v0.y*inv);
    __nv_bfloat162 h1 = __floats2bfloat162_rn(v0.z*inv, v0.w*inv);
    __nv_bfloat162 h2 = __floats2bfloat162_rn(v1.x*inv, v1.y*inv);
    __nv_bfloat162 h3 = __floats2bfloat162_rn(v1.z*inv, v1.w*inv);
    uint4 u;
    u.x = *(unsigned*)&h0; u.y = *(unsigned*)&h1;
    u.z = *(unsigned*)&h2; u.w = *(unsigned*)&h3;
    *(uint4*)(g_zn + (size_t)row * DIM + lane * 8) = u;
    if (lane == 0) { g_sumexp[row] = 0.0f; g_pos[row] = 0.0f; }
}

// ---------------------------------------------------------------------------
// fast exp via 2^y on the FMA pipe (MUFU would bottleneck at 0.5 op/cyc/SM)
// ---------------------------------------------------------------------------
__device__ __forceinline__ float fast_exp2(float y) {
    float t  = y + 12582912.0f;          // round-to-nearest-int trick (1.5*2^23)
    int   i  = __float_as_int(t);
    float nf = t - 12582912.0f;
    float f  = y - nf;                   // f in [-0.5, 0.5]
    float p  = fmaf(1.3333558e-3f, f, 9.6181291e-3f);
    p = fmaf(p, f, 5.5504109e-2f);
    p = fmaf(p, f, 2.4022651e-1f);
    p = fmaf(p, f, 6.9314718e-1f);
    p = fmaf(p, f, 1.0f);
    return p * __int_as_float((i << 23) + 0x3F800000);
}

__device__ __forceinline__ void mma16816(float c[4],
                                         unsigned a0, unsigned a1, unsigned a2, unsigned a3,
                                         unsigned b0, unsigned b1) {
    asm volatile(
        "mma.sync.aligned.m16n8k16.row.col.f32.bf16.bf16.f32 "
        "{%0,%1,%2,%3}, {%4,%5,%6,%7}, {%8,%9}, {%0,%1,%2,%3};\n"
        : "+f"(c[0]), "+f"(c[1]), "+f"(c[2]), "+f"(c[3])
        : "r"(a0), "r"(a1), "r"(a2), "r"(a3), "r"(b0), "r"(b1));
}

// ---------------------------------------------------------------------------
// Kernel B: symmetric bf16 GEMM (upper-triangle tiles only) with fused
// exp + diagonal mask + row AND column sum-of-exp.
// A tile (full K=256) resident per block; B loaded per-tile in two K=128
// chunks so smem fits 2 CTAs/SM -> inter-CTA overlap keeps tensor pipe busy.
// ---------------------------------------------------------------------------
__global__ void __launch_bounds__(256, 2) ntxent_gemm_kernel() {
    extern __shared__ __nv_bfloat16 smem[];
    __nv_bfloat16* As = smem;                           // 128 x 264
    __nv_bfloat16* Bs = smem + TILE_M * A_STRIDE;       // 128 x 136 (one K-chunk)

    int tid  = threadIdx.x;
    int warp = tid >> 5, lane = tid & 31;
    int g    = lane >> 2, tig = lane & 3;
    int wm   = warp >> 2, wn = warp & 3;      // 2x4 warp grid -> 64x32 per warp

    int iTile   = blockIdx.x;
    int rowbase = iTile * TILE_M;

    // Load A tile once (128 x 256 bf16)
    {
        const uint4* gsrc = (const uint4*)(g_zn + (size_t)rowbase * DIM);
        #pragma unroll
        for (int it = 0; it < 16; it++) {
            int idx = tid + it * 256;
            int r = idx >> 5, c8 = idx & 31;
            *(uint4*)(As + r * A_STRIDE + c8 * 8) = gsrc[r * 32 + c8];
        }
    }

    float rsum[4][2];
    #pragma unroll
    for (int mt = 0; mt < 4; mt++) { rsum[mt][0] = 0.f; rsum[mt][1] = 0.f; }

    bool didWork = false;

    for (int t = 0; t < 16; t++) {
        int jTile = blockIdx.y * 16 + t;
        if (jTile < iTile) continue;          // symmetry: upper triangle only
        didWork = true;
        int colbase = jTile * TILE_M;

        float acc[4][4][4];
        #pragma unroll
        for (int mt = 0; mt < 4; mt++)
            #pragma unroll
            for (int nt = 0; nt < 4; nt++)
                #pragma unroll
                for (int ci = 0; ci < 4; ci++) acc[mt][nt][ci] = 0.f;

        // two K=128 chunks of B
        #pragma unroll
        for (int ch = 0; ch < 2; ch++) {
            __syncthreads();   // previous chunk compute done (A stores visible)
            {
                // load B chunk: 128 rows x 128 bf16 (= 16 uint4 per row)
                const uint4* gsrc = (const uint4*)(g_zn + (size_t)colbase * DIM + ch * 128);
                #pragma unroll
                for (int it = 0; it < 8; it++) {
                    int idx = tid + it * 256;            // 2048 uint4
                    int r = idx >> 4, c = idx & 15;
                    *(uint4*)(Bs + r * B_STRIDE + c * 8) = gsrc[r * 32 + c];
                }
            }
            __syncthreads();

            #pragma unroll
            for (int kk = 0; kk < 8; kk++) {
                int ka = ch * 128 + kk * 16 + tig * 2;   // A k-offset
                int kb = kk * 16 + tig * 2;              // B chunk k-offset
                unsigned a[4][4], b[4][2];
                #pragma unroll
                for (int mt = 0; mt < 4; mt++) {
                    const __nv_bfloat16* ap = As + (wm * 64 + mt * 16 + g) * A_STRIDE + ka;
                    a[mt][0] = *(const unsigned*)(ap);
                    a[mt][1] = *(const unsigned*)(ap + 8 * A_STRIDE);
                    a[mt][2] = *(const unsigned*)(ap + 8);
                    a[mt][3] = *(const unsigned*)(ap + 8 * A_STRIDE + 8);
                }
                #pragma unroll
                for (int nt = 0; nt < 4; nt++) {
                    const __nv_bfloat16* bp = Bs + (wn * 32 + nt * 8 + g) * B_STRIDE + kb;
                    b[nt][0] = *(const unsigned*)(bp);
                    b[nt][1] = *(const unsigned*)(bp + 8);
                }
                #pragma unroll
                for (int mt = 0; mt < 4; mt++)
                    #pragma unroll
                    for (int nt = 0; nt < 4; nt++)
                        mma16816(acc[mt][nt], a[mt][0], a[mt][1], a[mt][2], a[mt][3],
                                 b[nt][0], b[nt][1]);
            }
        }

        if (jTile == iTile) {
            // Diagonal tile: row sums only, exact diagonal mask.
            #pragma unroll
            for (int mt = 0; mt < 4; mt++) {
                int row0 = rowbase + wm * 64 + mt * 16 + g;
                #pragma unroll
                for (int nt = 0; nt < 4; nt++) {
                    int col0 = colbase + wn * 32 + nt * 8 + tig * 2;
                    #pragma unroll
                    for (int ci = 0; ci < 4; ci++) {
                        int row = row0 + (ci >> 1) * 8;
                        int col = col0 + (ci & 1);
                        float e = fast_exp2(acc[mt][nt][ci] * (INV_T * LOG2E));
                        if (col == row) e = 0.0f;
                        rsum[mt][ci >> 1] += e;
                    }
                }
            }
        } else {
            float csum[4][2];
            #pragma unroll
            for (int nt = 0; nt < 4; nt++) { csum[nt][0] = 0.f; csum[nt][1] = 0.f; }

            bool hasPos = (jTile == iTile + 32);   // contains sim[r, r+4096]
            if (hasPos) {
                #pragma unroll
                for (int mt = 0; mt < 4; mt++) {
                    int row0 = rowbase + wm * 64 + mt * 16 + g;
                    #pragma unroll
                    for (int nt = 0; nt < 4; nt++) {
                        int col0 = colbase + wn * 32 + nt * 8 + tig * 2;
                        #pragma unroll
                        for (int ci = 0; ci < 4; ci++) {
                            int row = row0 + (ci >> 1) * 8;
                            int col = col0 + (ci & 1);
                            float v = acc[mt][nt][ci];
                            float e = fast_exp2(v * (INV_T * LOG2E));
                            if (col == row + BHALF) {      // positive pair (both dirs)
                                g_pos[row] = v * INV_T;
                                g_pos[col] = v * INV_T;
                            }
                            rsum[mt][ci >> 1] += e;
                            csum[nt][ci & 1]  += e;
                        }
                    }
                }
            } else {
                #pragma unroll
                for (int mt = 0; mt < 4; mt++) {
                    #pragma unroll
                    for (int nt = 0; nt < 4; nt++) {
                        #pragma unroll
                        for (int ci = 0; ci < 4; ci++) {
                            float e = fast_exp2(acc[mt][nt][ci] * (INV_T * LOG2E));
                            rsum[mt][ci >> 1] += e;
                            csum[nt][ci & 1]  += e;
                        }
                    }
                }
            }

            // Column reduction: sum over g lanes (xor 4,8,16), then atomic.
            #pragma unroll
            for (int nt = 0; nt < 4; nt++) {
                #pragma unroll
                for (int p = 0; p < 2; p++) {
                    float v = csum[nt][p];
                    v += __shfl_xor_sync(0xffffffffu, v, 4);
                    v += __shfl_xor_sync(0xffffffffu, v, 8);
                    v += __shfl_xor_sync(0xffffffffu, v, 16);
                    if (g == 0) {
                        int col = colbase + wn * 32 + nt * 8 + tig * 2 + p;
                        atomicAdd(&g_sumexp[col], v);
                    }
                }
            }
        }
    }

    if (!didWork) return;

    // Reduce row sums across the 4 lanes (tig) sharing each row, then global
    #pragma unroll
    for (int mt = 0; mt < 4; mt++) {
        #pragma unroll
        for (int h = 0; h < 2; h++) {
            float v = rsum[mt][h];
            v += __shfl_xor_sync(0xffffffffu, v, 1);
            v += __shfl_xor_sync(0xffffffffu, v, 2);
            if (tig == 0) {
                int row = rowbase + wm * 64 + mt * 16 + g + h * 8;
                atomicAdd(&g_sumexp[row], v);
            }
        }
    }
}

// ---------------------------------------------------------------------------
// Kernel C: loss = mean_k( log(sumexp_k) - pos_k )
// ---------------------------------------------------------------------------
__global__ void loss_kernel(float* __restrict__ out) {
    int tid = threadIdx.x;  // 1024
    float s = 0.0f;
    for (int k = tid; k < NROW; k += 1024)
        s += logf(g_sumexp[k]) - g_pos[k];
    #pragma unroll
    for (int o = 16; o; o >>= 1) s += __shfl_xor_sync(0xffffffffu, s, o);
    __shared__ float sw[32];
    if ((tid & 31) == 0) sw[tid >> 5] = s;
    __syncthreads();
    if (tid < 32) {
        float v = sw[tid];
        #pragma unroll
        for (int o = 16; o; o >>= 1) v += __shfl_xor_sync(0xffffffffu, v, o);
        if (tid == 0) out[0] = v / (float)NROW;
    }
}

extern "C" void kernel_launch(void* const* d_in, const int* in_sizes, int n_in,
                              void* d_out, int out_size) {
    const float* z_i = (const float*)d_in[0];
    const float* z_j = (const float*)d_in[1];
    float* out = (float*)d_out;

    cudaFuncSetAttribute(ntxent_gemm_kernel,
                         cudaFuncAttributeMaxDynamicSharedMemorySize, SMEM_BYTES);

    normalize_kernel<<<NROW / 8, 256>>>(z_i, z_j);
    ntxent_gemm_kernel<<<dim3(64, 4), 256, SMEM_BYTES>>>();
    loss_kernel<<<1, 1024>>>(out);
}

// round 7
// speedup vs baseline: 3.5168x; 1.6682x over previous
#include <cuda_runtime.h>
#include <cuda_bf16.h>

#define BHALF 4096
#define NROW  8192
#define DIM   256
#define INV_T (1.0f/0.07f)
#define LOG2E 1.4426950408889634f

#define TILE_M 128
#define SM_STRIDE 264            // 256 + 8 bf16 pad -> conflict-free fragment loads
#define TILE_BYTES (TILE_M * SM_STRIDE * 2)          // 67584
#define SMEM_BYTES (3 * TILE_BYTES)                  // A + 2x B = 202752

#define NTILE 64                 // 8192 / 128
#define NPAIR 2080               // upper-triangle tile count
#define NBLK  148                // persistent blocks (1 per SM)

__device__ __nv_bfloat16 g_zn[NROW * DIM];   // normalized rows, bf16 (4 MB)
__device__ float g_sumexp[NROW];
__device__ float g_pos[NROW];

// ---------------------------------------------------------------------------
// Kernel A: L2-normalize rows of concat(z_i, z_j) -> bf16; zero accumulators
// ---------------------------------------------------------------------------
__global__ void normalize_kernel(const float* __restrict__ z_i,
                                 const float* __restrict__ z_j) {
    int warp = threadIdx.x >> 5, lane = threadIdx.x & 31;
    int row  = blockIdx.x * 8 + warp;
    const float* src = (row < BHALF) ? (z_i + (size_t)row * DIM)
                                     : (z_j + (size_t)(row - BHALF) * DIM);
    float4 v0 = ((const float4*)src)[lane * 2];
    float4 v1 = ((const float4*)src)[lane * 2 + 1];
    float ss = v0.x*v0.x + v0.y*v0.y + v0.z*v0.z + v0.w*v0.w
             + v1.x*v1.x + v1.y*v1.y + v1.z*v1.z + v1.w*v1.w;
    #pragma unroll
    for (int o = 16; o; o >>= 1) ss += __shfl_xor_sync(0xffffffffu, ss, o);
    float inv = 1.0f / fmaxf(sqrtf(ss), 1e-8f);

    __nv_bfloat162 h0 = __floats2bfloat162_rn(v0.x*inv, v0.y*inv);
    __nv_bfloat162 h1 = __floats2bfloat162_rn(v0.z*inv, v0.w*inv);
    __nv_bfloat162 h2 = __floats2bfloat162_rn(v1.x*inv, v1.y*inv);
    __nv_bfloat162 h3 = __floats2bfloat162_rn(v1.z*inv, v1.w*inv);
    uint4 u;
    u.x = *(unsigned*)&h0; u.y = *(unsigned*)&h1;
    u.z = *(unsigned*)&h2; u.w = *(unsigned*)&h3;
    *(uint4*)(g_zn + (size_t)row * DIM + lane * 8) = u;
    if (lane == 0) { g_sumexp[row] = 0.0f; g_pos[row] = 0.0f; }
}

// ---------------------------------------------------------------------------
// fast exp via 2^y on the FMA pipe
// ---------------------------------------------------------------------------
__device__ __forceinline__ float fast_exp2(float y) {
    float t  = y + 12582912.0f;          // round-to-nearest-int trick (1.5*2^23)
    int   i  = __float_as_int(t);
    float nf = t - 12582912.0f;
    float f  = y - nf;                   // f in [-0.5, 0.5]
    float p  = fmaf(1.3333558e-3f, f, 9.6181291e-3f);
    p = fmaf(p, f, 5.5504109e-2f);
    p = fmaf(p, f, 2.4022651e-1f);
    p = fmaf(p, f, 6.9314718e-1f);
    p = fmaf(p, f, 1.0f);
    return p * __int_as_float((i << 23) + 0x3F800000);
}

__device__ __forceinline__ void mma16816(float c[4],
                                         unsigned a0, unsigned a1, unsigned a2, unsigned a3,
                                         unsigned b0, unsigned b1) {
    asm volatile(
        "mma.sync.aligned.m16n8k16.row.col.f32.bf16.bf16.f32 "
        "{%0,%1,%2,%3}, {%4,%5,%6,%7}, {%8,%9}, {%0,%1,%2,%3};\n"
        : "+f"(c[0]), "+f"(c[1]), "+f"(c[2]), "+f"(c[3])
        : "r"(a0), "r"(a1), "r"(a2), "r"(a3), "r"(b0), "r"(b1));
}

__device__ __forceinline__ void cp_async16(void* smem_dst, const void* gsrc) {
    unsigned s = (unsigned)__cvta_generic_to_shared(smem_dst);
    asm volatile("cp.async.cg.shared.global [%0], [%1], 16;\n" :: "r"(s), "l"(gsrc));
}
__device__ __forceinline__ void cp_commit() {
    asm volatile("cp.async.commit_group;\n" ::: "memory");
}
__device__ __forceinline__ void cp_wait1() {
    asm volatile("cp.async.wait_group 1;\n" ::: "memory");
}
__device__ __forceinline__ void cp_wait0() {
    asm volatile("cp.async.wait_group 0;\n" ::: "memory");
}

__device__ __forceinline__ void load_tile_cp(__nv_bfloat16* dst,
                                             const __nv_bfloat16* src, int tid) {
    #pragma unroll
    for (int it = 0; it < 16; it++) {
        int idx = tid + it * 256;          // 4096 16B chunks
        int r = idx >> 5, c8 = idx & 31;
        cp_async16(dst + r * SM_STRIDE + c8 * 8, src + r * 256 + c8 * 8);
    }
}

__device__ __forceinline__ void load_tile_sync(__nv_bfloat16* dst,
                                               const __nv_bfloat16* src, int tid) {
    const uint4* gsrc = (const uint4*)src;
    #pragma unroll
    for (int it = 0; it < 16; it++) {
        int idx = tid + it * 256;
        int r = idx >> 5, c8 = idx & 31;
        *(uint4*)(dst + r * SM_STRIDE + c8 * 8) = gsrc[r * 32 + c8];
    }
}

// decode linear upper-triangle tile index q -> (i, j)
__device__ __forceinline__ void decode_tile(int q, int& i, int& j) {
    i = 0;
    int rem = q;
    while (rem >= NTILE - i) { rem -= NTILE - i; i++; }
    j = i + rem;
}

__device__ __forceinline__ void flush_rsum(float (&rsum)[4][2], int iT,
                                           int wm, int g, int tig) {
    #pragma unroll
    for (int mt = 0; mt < 4; mt++)
        #pragma unroll
        for (int h = 0; h < 2; h++) {
            float v = rsum[mt][h];
            v += __shfl_xor_sync(0xffffffffu, v, 1);
            v += __shfl_xor_sync(0xffffffffu, v, 2);
            if (tig == 0)
                atomicAdd(&g_sumexp[iT * TILE_M + wm * 64 + mt * 16 + g + h * 8], v);
            rsum[mt][h] = 0.0f;
        }
}

// column-sum reduce + atomics for tile jP (skip for diagonal tiles)
__device__ __forceinline__ void flush_csum(float (&csum)[4][2], int jP,
                                           int wn, int g, int tig) {
    #pragma unroll
    for (int nt = 0; nt < 4; nt++)
        #pragma unroll
        for (int p = 0; p < 2; p++) {
            float v = csum[nt][p];
            v += __shfl_xor_sync(0xffffffffu, v, 4);
            v += __shfl_xor_sync(0xffffffffu, v, 8);
            v += __shfl_xor_sync(0xffffffffu, v, 16);
            if (g == 0)
                atomicAdd(&g_sumexp[jP * TILE_M + wn * 32 + nt * 8 + tig * 2 + p], v);
        }
}

// ---------------------------------------------------------------------------
// MMA over tile (iCur) with epilogue of tile (iP,jP) interleaved into the
// kk-step stream: chunk kk handles prev fragment (mt=kk>>2, nt=kk&3).
// ---------------------------------------------------------------------------
__device__ __forceinline__ void mma_tile(
    const __nv_bfloat16* __restrict__ As, const __nv_bfloat16* __restrict__ Bb,
    float (&cur)[4][4][4], float (&prev)[4][4][4],
    bool havePrev, int iP, int jP, float (&rsum)[4][2],
    int wm, int wn, int g, int tig)
{
    float csum[4][2];
    #pragma unroll
    for (int nt = 0; nt < 4; nt++) { csum[nt][0] = 0.f; csum[nt][1] = 0.f; }
    #pragma unroll
    for (int mt = 0; mt < 4; mt++)
        #pragma unroll
        for (int nt = 0; nt < 4; nt++)
            #pragma unroll
            for (int ci = 0; ci < 4; ci++) cur[mt][nt][ci] = 0.f;

    const bool diag = (iP == jP);
    const bool pos  = (jP == iP + 32);

    #pragma unroll
    for (int kk = 0; kk < 16; kk++) {
        const int k0 = kk * 16 + tig * 2;
        unsigned a[4][4], b[4][2];
        #pragma unroll
        for (int mt = 0; mt < 4; mt++) {
            const __nv_bfloat16* ap = As + (wm * 64 + mt * 16 + g) * SM_STRIDE + k0;
            a[mt][0] = *(const unsigned*)(ap);
            a[mt][1] = *(const unsigned*)(ap + 8 * SM_STRIDE);
            a[mt][2] = *(const unsigned*)(ap + 8);
            a[mt][3] = *(const unsigned*)(ap + 8 * SM_STRIDE + 8);
        }
        #pragma unroll
        for (int nt = 0; nt < 4; nt++) {
            const __nv_bfloat16* bp = Bb + (wn * 32 + nt * 8 + g) * SM_STRIDE + k0;
            b[nt][0] = *(const unsigned*)(bp);
            b[nt][1] = *(const unsigned*)(bp + 8);
        }
        #pragma unroll
        for (int mt = 0; mt < 4; mt++)
            #pragma unroll
            for (int nt = 0; nt < 4; nt++)
                mma16816(cur[mt][nt], a[mt][0], a[mt][1], a[mt][2], a[mt][3],
                         b[nt][0], b[nt][1]);

        // interleaved epilogue chunk of previous tile (fills HMMA issue gaps)
        if (havePrev) {
            const int mt = kk >> 2, nt = kk & 3;
            #pragma unroll
            for (int ci = 0; ci < 4; ci++) {
                float v = prev[mt][nt][ci];
                float e = fast_exp2(v * (INV_T * LOG2E));
                if (diag | pos) {
                    int row = iP * TILE_M + wm * 64 + mt * 16 + g + (ci >> 1) * 8;
                    int col = jP * TILE_M + wn * 32 + nt * 8 + tig * 2 + (ci & 1);
                    if (pos & (col == row + BHALF)) {
                        float pv = v * INV_T;
                        g_pos[row] = pv;
                        g_pos[col] = pv;
                    }
                    if (diag & (col == row)) e = 0.0f;
                }
                rsum[mt][ci >> 1] += e;
                csum[nt][ci & 1]  += e;
            }
        }
    }

    if (havePrev && !diag) flush_csum(csum, jP, wn, g, tig);
}

// standalone epilogue (for the final tile of a block's range)
__device__ __forceinline__ void epi_tile(
    float (&prev)[4][4][4], int iP, int jP, float (&rsum)[4][2],
    int wm, int wn, int g, int tig)
{
    float csum[4][2];
    #pragma unroll
    for (int nt = 0; nt < 4; nt++) { csum[nt][0] = 0.f; csum[nt][1] = 0.f; }
    const bool diag = (iP == jP);
    const bool pos  = (jP == iP + 32);
    #pragma unroll
    for (int mt = 0; mt < 4; mt++)
        #pragma unroll
        for (int nt = 0; nt < 4; nt++)
            #pragma unroll
            for (int ci = 0; ci < 4; ci++) {
                float v = prev[mt][nt][ci];
                float e = fast_exp2(v * (INV_T * LOG2E));
                if (diag | pos) {
                    int row = iP * TILE_M + wm * 64 + mt * 16 + g + (ci >> 1) * 8;
                    int col = jP * TILE_M + wn * 32 + nt * 8 + tig * 2 + (ci & 1);
                    if (pos & (col == row + BHALF)) {
                        float pv = v * INV_T;
                        g_pos[row] = pv;
                        g_pos[col] = pv;
                    }
                    if (diag & (col == row)) e = 0.0f;
                }
                rsum[mt][ci >> 1] += e;
                csum[nt][ci & 1]  += e;
            }
    if (!diag) flush_csum(csum, jP, wn, g, tig);
}

// ---------------------------------------------------------------------------
// Kernel B: persistent balanced symmetric bf16 GEMM over upper-triangle
// tiles; epilogue of tile t-1 interleaved into MMA of tile t (acc ping-pong);
// B double-buffered via cp.async; A reloaded only on row change.
// ---------------------------------------------------------------------------
__global__ void __launch_bounds__(256) ntxent_gemm_kernel() {
    extern __shared__ __nv_bfloat16 smem[];
    __nv_bfloat16* As  = smem;
    __nv_bfloat16* Bs0 = smem + TILE_M * SM_STRIDE;
    __nv_bfloat16* Bs1 = Bs0 + TILE_M * SM_STRIDE;

    int tid  = threadIdx.x;
    int warp = tid >> 5, lane = tid & 31;
    int g    = lane >> 2, tig = lane & 3;
    int wm   = warp >> 2, wn = warp & 3;      // 2x4 warp grid -> 64x32 per warp

    int bid = blockIdx.x;
    int q0  = (int)(((long long)bid * NPAIR) / NBLK);
    int q1  = (int)(((long long)(bid + 1) * NPAIR) / NBLK);

    int iCur, jCur;
    decode_tile(q0, iCur, jCur);

    // prologue: A synchronous, B(q0) via cp.async into Bs0
    load_tile_sync(As, g_zn + (size_t)iCur * TILE_M * DIM, tid);
    int iLoaded = iCur;
    load_tile_cp(Bs0, g_zn + (size_t)jCur * TILE_M * DIM, tid);
    cp_commit();

    float accA[4][4][4], accB[4][4][4];
    float rsum[4][2];
    #pragma unroll
    for (int mt = 0; mt < 4; mt++) { rsum[mt][0] = 0.f; rsum[mt][1] = 0.f; }

    int iP = -1, jP = -1;
    bool phaseA = true;

    for (int q = q0; q < q1; q++) {
        int buf = (q - q0) & 1;
        int iN = iCur, jN = jCur + 1;
        if (jN == NTILE) { iN++; jN = iN; }

        __syncthreads();                    // all warps done with Bs[buf^1]

        if (q + 1 < q1)
            load_tile_cp(buf ? Bs0 : Bs1, g_zn + (size_t)jN * TILE_M * DIM, tid);
        cp_commit();                        // uniform group count

        if (iCur != iLoaded) {              // row changed: reload A (sync)
            load_tile_sync(As, g_zn + (size_t)iCur * TILE_M * DIM, tid);
            iLoaded = iCur;
        }

        cp_wait1();                         // B(t) complete; B(t+1) in flight
        __syncthreads();

        const __nv_bfloat16* Bb = buf ? Bs1 : Bs0;
        if (phaseA) mma_tile(As, Bb, accA, accB, iP >= 0, iP, jP, rsum, wm, wn, g, tig);
        else        mma_tile(As, Bb, accB, accA, iP >= 0, iP, jP, rsum, wm, wn, g, tig);
        phaseA = !phaseA;

        if (iP >= 0 && iP != iCur)          // epi of row iP is now complete
            flush_rsum(rsum, iP, wm, g, tig);

        iP = iCur; jP = jCur;
        iCur = iN; jCur = jN;
    }

    // final tile's epilogue (its acc is the one just written)
    if (phaseA) epi_tile(accB, iP, jP, rsum, wm, wn, g, tig);
    else        epi_tile(accA, iP, jP, rsum, wm, wn, g, tig);
    flush_rsum(rsum, iP, wm, g, tig);
    cp_wait0();
}

// ---------------------------------------------------------------------------
// Kernel C: loss = mean_k( log(sumexp_k) - pos_k )
// ---------------------------------------------------------------------------
__global__ void loss_kernel(float* __restrict__ out) {
    int tid = threadIdx.x;  // 1024
    float s = 0.0f;
    for (int k = tid; k < NROW; k += 1024)
        s += logf(g_sumexp[k]) - g_pos[k];
    #pragma unroll
    for (int o = 16; o; o >>= 1) s += __shfl_xor_sync(0xffffffffu, s, o);
    __shared__ float sw[32];
    if ((tid & 31) == 0) sw[tid >> 5] = s;
    __syncthreads();
    if (tid < 32) {
        float v = sw[tid];
        #pragma unroll
        for (int o = 16; o; o >>= 1) v += __shfl_xor_sync(0xffffffffu, v, o);
        if (tid == 0) out[0] = v / (float)NROW;
    }
}

extern "C" void kernel_launch(void* const* d_in, const int* in_sizes, int n_in,
                              void* d_out, int out_size) {
    const float* z_i = (const float*)d_in[0];
    const float* z_j = (const float*)d_in[1];
    float* out = (float*)d_out;

    cudaFuncSetAttribute(ntxent_gemm_kernel,
                         cudaFuncAttributeMaxDynamicSharedMemorySize, SMEM_BYTES);

    normalize_kernel<<<NROW / 8, 256>>>(z_i, z_j);
    ntxent_gemm_kernel<<<NBLK, 256, SMEM_BYTES>>>();
    loss_kernel<<<1, 1024>>>(out);
}

// round 8
// speedup vs baseline: 3.5296x; 1.0036x over previous
#include <cuda_runtime.h>
#include <cuda_bf16.h>

#define BHALF 4096
#define NROW  8192
#define DIM   256
#define INV_T (1.0f/0.07f)
#define LOG2E 1.4426950408889634f

#define TILE_M 128
#define SM_STRIDE 264            // 256 + 8 bf16 pad -> conflict-free fragment loads
#define TILE_BYTES (TILE_M * SM_STRIDE * 2)          // 67584
#define SMEM_BYTES (3 * TILE_BYTES)                  // A + 2x B = 202752

#define NTILE 64                 // 8192 / 128
#define NPAIR 2080               // upper-triangle tile count

__device__ __nv_bfloat16 g_zn[NROW * DIM];   // normalized rows, bf16 (4 MB)
__device__ float g_sumexp[NROW];
__device__ float g_pos[NROW];
__device__ volatile unsigned g_gen;          // grid-barrier generation (monotonic)
__device__ unsigned g_count;                 // grid-barrier arrival count
__device__ unsigned g_done;                  // tail: last-block election

// ---------------------------------------------------------------------------
// soft grid barrier (single-wave persistent grid only)
// ---------------------------------------------------------------------------
__device__ __forceinline__ void grid_barrier(unsigned nblk) {
    __threadfence();             // every thread publishes its writes
    __syncthreads();
    if (threadIdx.x == 0) {
        unsigned gen = g_gen;
        if (atomicAdd(&g_count, 1) == nblk - 1) {
            g_count = 0;
            __threadfence();
            g_gen = gen + 1;     // release
        } else {
            while (g_gen == gen) {}
            __threadfence();     // acquire
        }
    }
    __syncthreads();
}

// ---------------------------------------------------------------------------
// fast exp via 2^y on the FMA pipe
// ---------------------------------------------------------------------------
__device__ __forceinline__ float fast_exp2(float y) {
    float t  = y + 12582912.0f;          // round-to-nearest-int trick (1.5*2^23)
    int   i  = __float_as_int(t);
    float nf = t - 12582912.0f;
    float f  = y - nf;                   // f in [-0.5, 0.5]
    float p  = fmaf(1.3333558e-3f, f, 9.6181291e-3f);
    p = fmaf(p, f, 5.5504109e-2f);
    p = fmaf(p, f, 2.4022651e-1f);
    p = fmaf(p, f, 6.9314718e-1f);
    p = fmaf(p, f, 1.0f);
    return p * __int_as_float((i << 23) + 0x3F800000);
}

__device__ __forceinline__ void mma16816(float c[4],
                                         unsigned a0, unsigned a1, unsigned a2, unsigned a3,
                                         unsigned b0, unsigned b1) {
    asm volatile(
        "mma.sync.aligned.m16n8k16.row.col.f32.bf16.bf16.f32 "
        "{%0,%1,%2,%3}, {%4,%5,%6,%7}, {%8,%9}, {%0,%1,%2,%3};\n"
        : "+f"(c[0]), "+f"(c[1]), "+f"(c[2]), "+f"(c[3])
        : "r"(a0), "r"(a1), "r"(a2), "r"(a3), "r"(b0), "r"(b1));
}

__device__ __forceinline__ void cp_async16(void* smem_dst, const void* gsrc) {
    unsigned s = (unsigned)__cvta_generic_to_shared(smem_dst);
    asm volatile("cp.async.cg.shared.global [%0], [%1], 16;\n" :: "r"(s), "l"(gsrc));
}
__device__ __forceinline__ void cp_commit() {
    asm volatile("cp.async.commit_group;\n" ::: "memory");
}
__device__ __forceinline__ void cp_wait1() {
    asm volatile("cp.async.wait_group 1;\n" ::: "memory");
}
__device__ __forceinline__ void cp_wait0() {
    asm volatile("cp.async.wait_group 0;\n" ::: "memory");
}

__device__ __forceinline__ void load_tile_cp(__nv_bfloat16* dst,
                                             const __nv_bfloat16* src, int tid) {
    #pragma unroll
    for (int it = 0; it < 16; it++) {
        int idx = tid + it * 256;          // 4096 16B chunks
        int r = idx >> 5, c8 = idx & 31;
        cp_async16(dst + r * SM_STRIDE + c8 * 8, src + r * 256 + c8 * 8);
    }
}

__device__ __forceinline__ void load_tile_sync(__nv_bfloat16* dst,
                                               const __nv_bfloat16* src, int tid) {
    const uint4* gsrc = (const uint4*)src;
    #pragma unroll
    for (int it = 0; it < 16; it++) {
        int idx = tid + it * 256;
        int r = idx >> 5, c8 = idx & 31;
        *(uint4*)(dst + r * SM_STRIDE + c8 * 8) = gsrc[r * 32 + c8];
    }
}

// decode linear upper-triangle tile index q -> (i, j)
__device__ __forceinline__ void decode_tile(int q, int& i, int& j) {
    i = 0;
    int rem = q;
    while (rem >= NTILE - i) { rem -= NTILE - i; i++; }
    j = i + rem;
}

__device__ __forceinline__ void flush_rsum(float (&rsum)[4][2], int iT,
                                           int wm, int g, int tig) {
    #pragma unroll
    for (int mt = 0; mt < 4; mt++)
        #pragma unroll
        for (int h = 0; h < 2; h++) {
            float v = rsum[mt][h];
            v += __shfl_xor_sync(0xffffffffu, v, 1);
            v += __shfl_xor_sync(0xffffffffu, v, 2);
            if (tig == 0)
                atomicAdd(&g_sumexp[iT * TILE_M + wm * 64 + mt * 16 + g + h * 8], v);
            rsum[mt][h] = 0.0f;
        }
}

__device__ __forceinline__ void flush_csum(float (&csum)[4][2], int jP,
                                           int wn, int g, int tig) {
    #pragma unroll
    for (int nt = 0; nt < 4; nt++)
        #pragma unroll
        for (int p = 0; p < 2; p++) {
            float v = csum[nt][p];
            v += __shfl_xor_sync(0xffffffffu, v, 4);
            v += __shfl_xor_sync(0xffffffffu, v, 8);
            v += __shfl_xor_sync(0xffffffffu, v, 16);
            if (g == 0)
                atomicAdd(&g_sumexp[jP * TILE_M + wn * 32 + nt * 8 + tig * 2 + p], v);
        }
}

// ---------------------------------------------------------------------------
// MMA over current tile with epilogue of tile (iP,jP) interleaved into the
// kk-step stream: chunk kk handles prev fragment (mt=kk>>2, nt=kk&3).
// ---------------------------------------------------------------------------
__device__ __forceinline__ void mma_tile(
    const __nv_bfloat16* __restrict__ As, const __nv_bfloat16* __restrict__ Bb,
    float (&cur)[4][4][4], float (&prev)[4][4][4],
    bool havePrev, int iP, int jP, float (&rsum)[4][2],
    int wm, int wn, int g, int tig)
{
    float csum[4][2];
    #pragma unroll
    for (int nt = 0; nt < 4; nt++) { csum[nt][0] = 0.f; csum[nt][1] = 0.f; }
    #pragma unroll
    for (int mt = 0; mt < 4; mt++)
        #pragma unroll
        for (int nt = 0; nt < 4; nt++)
            #pragma unroll
            for (int ci = 0; ci < 4; ci++) cur[mt][nt][ci] = 0.f;

    const bool diag = (iP == jP);
    const bool pos  = (jP == iP + 32);

    #pragma unroll
    for (int kk = 0; kk < 16; kk++) {
        const int k0 = kk * 16 + tig * 2;
        unsigned a[4][4], b[4][2];
        #pragma unroll
        for (int mt = 0; mt < 4; mt++) {
            const __nv_bfloat16* ap = As + (wm * 64 + mt * 16 + g) * SM_STRIDE + k0;
            a[mt][0] = *(const unsigned*)(ap);
            a[mt][1] = *(const unsigned*)(ap + 8 * SM_STRIDE);
            a[mt][2] = *(const unsigned*)(ap + 8);
            a[mt][3] = *(const unsigned*)(ap + 8 * SM_STRIDE + 8);
        }
        #pragma unroll
        for (int nt = 0; nt < 4; nt++) {
            const __nv_bfloat16* bp = Bb + (wn * 32 + nt * 8 + g) * SM_STRIDE + k0;
            b[nt][0] = *(const unsigned*)(bp);
            b[nt][1] = *(const unsigned*)(bp + 8);
        }
        #pragma unroll
        for (int mt = 0; mt < 4; mt++)
            #pragma unroll
            for (int nt = 0; nt < 4; nt++)
                mma16816(cur[mt][nt], a[mt][0], a[mt][1], a[mt][2], a[mt][3],
                         b[nt][0], b[nt][1]);

        if (havePrev) {
            const int mt = kk >> 2, nt = kk & 3;
            #pragma unroll
            for (int ci = 0; ci < 4; ci++) {
                float v = prev[mt][nt][ci];
                float e = fast_exp2(v * (INV_T * LOG2E));
                if (diag | pos) {
                    int row = iP * TILE_M + wm * 64 + mt * 16 + g + (ci >> 1) * 8;
                    int col = jP * TILE_M + wn * 32 + nt * 8 + tig * 2 + (ci & 1);
                    if (pos & (col == row + BHALF)) {
                        float pv = v * INV_T;
                        g_pos[row] = pv;
                        g_pos[col] = pv;
                    }
                    if (diag & (col == row)) e = 0.0f;
                }
                rsum[mt][ci >> 1] += e;
                csum[nt][ci & 1]  += e;
            }
        }
    }

    if (havePrev && !diag) flush_csum(csum, jP, wn, g, tig);
}

__device__ __forceinline__ void epi_tile(
    float (&prev)[4][4][4], int iP, int jP, float (&rsum)[4][2],
    int wm, int wn, int g, int tig)
{
    float csum[4][2];
    #pragma unroll
    for (int nt = 0; nt < 4; nt++) { csum[nt][0] = 0.f; csum[nt][1] = 0.f; }
    const bool diag = (iP == jP);
    const bool pos  = (jP == iP + 32);
    #pragma unroll
    for (int mt = 0; mt < 4; mt++)
        #pragma unroll
        for (int nt = 0; nt < 4; nt++)
            #pragma unroll
            for (int ci = 0; ci < 4; ci++) {
                float v = prev[mt][nt][ci];
                float e = fast_exp2(v * (INV_T * LOG2E));
                if (diag | pos) {
                    int row = iP * TILE_M + wm * 64 + mt * 16 + g + (ci >> 1) * 8;
                    int col = jP * TILE_M + wn * 32 + nt * 8 + tig * 2 + (ci & 1);
                    if (pos & (col == row + BHALF)) {
                        float pv = v * INV_T;
                        g_pos[row] = pv;
                        g_pos[col] = pv;
                    }
                    if (diag & (col == row)) e = 0.0f;
                }
                rsum[mt][ci >> 1] += e;
                csum[nt][ci & 1]  += e;
            }
    if (!diag) flush_csum(csum, jP, wn, g, tig);
}

// ---------------------------------------------------------------------------
// one-warp row normalize: load fp32 row, L2-normalize, store bf16
// ---------------------------------------------------------------------------
__device__ __forceinline__ void norm_row(int row, const float* __restrict__ z_i,
                                         const float* __restrict__ z_j, int lane) {
    const float* src = (row < BHALF) ? (z_i + (size_t)row * DIM)
                                     : (z_j + (size_t)(row - BHALF) * DIM);
    float4 v0 = ((const float4*)src)[lane * 2];
    float4 v1 = ((const float4*)src)[lane * 2 + 1];
    float ss = v0.x*v0.x + v0.y*v0.y + v0.z*v0.z + v0.w*v0.w
             + v1.x*v1.x + v1.y*v1.y + v1.z*v1.z + v1.w*v1.w;
    #pragma unroll
    for (int o = 16; o; o >>= 1) ss += __shfl_xor_sync(0xffffffffu, ss, o);
    float inv = 1.0f / fmaxf(sqrtf(ss), 1e-8f);

    __nv_bfloat162 h0 = __floats2bfloat162_rn(v0.x*inv, v0.y*inv);
    __nv_bfloat162 h1 = __floats2bfloat162_rn(v0.z*inv, v0.w*inv);
    __nv_bfloat162 h2 = __floats2bfloat162_rn(v1.x*inv, v1.y*inv);
    __nv_bfloat162 h3 = __floats2bfloat162_rn(v1.z*inv, v1.w*inv);
    uint4 u;
    u.x = *(unsigned*)&h0; u.y = *(unsigned*)&h1;
    u.z = *(unsigned*)&h2; u.w = *(unsigned*)&h3;
    *(uint4*)(g_zn + (size_t)row * DIM + lane * 8) = u;
    if (lane == 0) { g_sumexp[row] = 0.0f; g_pos[row] = 0.0f; }
}

// ---------------------------------------------------------------------------
// fused persistent kernel: normalize -> grid barrier -> symmetric GEMM with
// fused softmax-sum epilogue -> last-block loss tail
// ---------------------------------------------------------------------------
__global__ void __launch_bounds__(256) ntxent_fused_kernel(
    const float* __restrict__ z_i, const float* __restrict__ z_j,
    float* __restrict__ out)
{
    extern __shared__ __nv_bfloat16 smem[];
    __nv_bfloat16* As  = smem;
    __nv_bfloat16* Bs0 = smem + TILE_M * SM_STRIDE;
    __nv_bfloat16* Bs1 = Bs0 + TILE_M * SM_STRIDE;

    const int tid  = threadIdx.x;
    const int warp = tid >> 5, lane = tid & 31;
    const int g    = lane >> 2, tig = lane & 3;
    const int wm   = warp >> 2, wn = warp & 3;
    const unsigned nblk = gridDim.x;

    // ---- phase 1: normalize (2 rows per warp in flight for MLP) ----
    {
        int stride = nblk * 8;
        for (int r0 = blockIdx.x * 8 + warp; r0 < NROW; r0 += 2 * stride) {
            int r1 = r0 + stride;
            norm_row(r0, z_i, z_j, lane);
            if (r1 < NROW) norm_row(r1, z_i, z_j, lane);
        }
    }

    grid_barrier(nblk);

    // ---- phase 2: GEMM over balanced contiguous triangle ranges ----
    int bid = blockIdx.x;
    int q0  = (int)(((long long)bid * NPAIR) / nblk);
    int q1  = (int)(((long long)(bid + 1) * NPAIR) / nblk);

    if (q0 < q1) {
        int iCur, jCur;
        decode_tile(q0, iCur, jCur);

        load_tile_sync(As, g_zn + (size_t)iCur * TILE_M * DIM, tid);
        int iLoaded = iCur;
        load_tile_cp(Bs0, g_zn + (size_t)jCur * TILE_M * DIM, tid);
        cp_commit();

        float accA[4][4][4], accB[4][4][4];
        float rsum[4][2];
        #pragma unroll
        for (int mt = 0; mt < 4; mt++) { rsum[mt][0] = 0.f; rsum[mt][1] = 0.f; }

        int iP = -1, jP = -1;
        bool phaseA = true;

        for (int q = q0; q < q1; q++) {
            int buf = (q - q0) & 1;
            int iN = iCur, jN = jCur + 1;
            if (jN == NTILE) { iN++; jN = iN; }

            __syncthreads();

            if (q + 1 < q1)
                load_tile_cp(buf ? Bs0 : Bs1, g_zn + (size_t)jN * TILE_M * DIM, tid);
            cp_commit();

            if (iCur != iLoaded) {
                load_tile_sync(As, g_zn + (size_t)iCur * TILE_M * DIM, tid);
                iLoaded = iCur;
            }

            cp_wait1();
            __syncthreads();

            const __nv_bfloat16* Bb = buf ? Bs1 : Bs0;
            if (phaseA) mma_tile(As, Bb, accA, accB, iP >= 0, iP, jP, rsum, wm, wn, g, tig);
            else        mma_tile(As, Bb, accB, accA, iP >= 0, iP, jP, rsum, wm, wn, g, tig);
            phaseA = !phaseA;

            if (iP >= 0 && iP != iCur)
                flush_rsum(rsum, iP, wm, g, tig);

            iP = iCur; jP = jCur;
            iCur = iN; jCur = jN;
        }

        if (phaseA) epi_tile(accB, iP, jP, rsum, wm, wn, g, tig);
        else        epi_tile(accA, iP, jP, rsum, wm, wn, g, tig);
        flush_rsum(rsum, iP, wm, g, tig);
        cp_wait0();
    }

    // ---- phase 3: last block computes the loss ----
    __threadfence();                 // publish this block's atomics/stores
    __syncthreads();
    __shared__ unsigned amLast;
    if (tid == 0)
        amLast = (atomicAdd(&g_done, 1) == nblk - 1) ? 1u : 0u;
    __syncthreads();

    if (amLast) {
        __threadfence();             // acquire: all blocks' results visible
        float s = 0.0f;
        for (int k = tid; k < NROW; k += 256)
            s += logf(__ldcg(&g_sumexp[k])) - __ldcg(&g_pos[k]);   // bypass L1
        #pragma unroll
        for (int o = 16; o; o >>= 1) s += __shfl_xor_sync(0xffffffffu, s, o);
        __shared__ float sw[8];
        if (lane == 0) sw[warp] = s;
        __syncthreads();
        if (tid == 0) {
            float v = 0.0f;
            #pragma unroll
            for (int w = 0; w < 8; w++) v += sw[w];
            out[0] = v / (float)NROW;
            g_done = 0;              // reset for next graph replay
        }
    }
}

extern "C" void kernel_launch(void* const* d_in, const int* in_sizes, int n_in,
                              void* d_out, int out_size) {
    const float* z_i = (const float*)d_in[0];
    const float* z_j = (const float*)d_in[1];
    float* out = (float*)d_out;

    int dev = 0, nsm = 148;
    cudaGetDevice(&dev);
    cudaDeviceGetAttribute(&nsm, cudaDevAttrMultiProcessorCount, dev);
    if (nsm < 1) nsm = 148;
    if (nsm > 512) nsm = 512;

    cudaFuncSetAttribute(ntxent_fused_kernel,
                         cudaFuncAttributeMaxDynamicSharedMemorySize, SMEM_BYTES);

    ntxent_fused_kernel<<<nsm, 256, SMEM_BYTES>>>(z_i, z_j, out);
}